// round 1
// baseline (speedup 1.0000x reference)
#include <cuda_runtime.h>

namespace {

constexpr int MUL  = 16;
constexpr int D    = 4;
constexpr int S1   = 8;
constexpr int SOUT = 8;
constexpr int NP3  = 8;
constexpr int NP4  = 4;

constexpr int X0_ROW  = 8 * MUL * D;     // 512 floats per x0 row
constexpr int X1_ROW  = S1 * D;          // 32
constexpr int OUT_ROW = SOUT * MUL * D;  // 512

constexpr int EPB     = 16;              // edges per block
constexpr int THREADS = 256;             // 16 lanes (u) per edge

__global__ void __launch_bounds__(THREADS)
tp_fused_kernel(const float* __restrict__ x0,
                const int*   __restrict__ i0,
                const float* __restrict__ x1,
                const float* __restrict__ gC3,
                const float* __restrict__ gC4,
                const int*   __restrict__ gp3,
                const int*   __restrict__ gp4,
                float*       __restrict__ out,
                int E)
{
    __shared__ __align__(16) float sC3[NP3 * 64];        // [p][i][j][k]
    __shared__ __align__(16) float sC4[NP4 * 256];       // [p][i][j][k][m]
    __shared__ int   sp3[NP3 * 3];
    __shared__ int   sp4[NP4 * 4];
    __shared__ __align__(16) float sx1[EPB][X1_ROW];     // per-edge x1 row
    __shared__ __align__(16) float sw3[EPB][NP3][16];    // [i*4+k]
    __shared__ __align__(16) float sw4[EPB][NP4][16];    // [i*4+m]

    const int tid = threadIdx.x;

    // ---- stage constants to shared (once per block) ----
    for (int t = tid; t < NP3 * 64;  t += THREADS) sC3[t] = gC3[t];
    for (int t = tid; t < NP4 * 256; t += THREADS) sC4[t] = gC4[t];
    if (tid < NP3 * 3)                        sp3[tid]            = gp3[tid];
    else if (tid < NP3 * 3 + NP4 * 4)         sp4[tid - NP3 * 3]  = gp4[tid - NP3 * 3];
    __syncthreads();

    const int  el   = tid >> 4;     // edge within block (0..15)
    const int  lane = tid & 15;     // u index (0..15)
    const long e    = (long)blockIdx.x * EPB + el;
    const bool active = (e < (long)E);

    // ---- stage this edge's x1 row ----
    if (active) {
        const float* xr = x1 + e * X1_ROW;
        sx1[el][lane]      = xr[lane];
        sx1[el][lane + 16] = xr[lane + 16];
    }
    __syncwarp();

    // ---- phase 1: per-edge factored path weights (shared across the 16 u-lanes) ----
    // lane -> (i_idx, km): each lane owns one (i, k/m) cell for every path.
    {
        const int i_idx = lane >> 2;
        const int km    = lane & 3;
        const float* bx = sx1[el];

        #pragma unroll
        for (int p = 0; p < NP3; p++) {
            const float* b = bx + sp3[p * 3 + 1] * 4;
            const float* c = sC3 + p * 64 + i_idx * 16 + km;   // j stride = 4
            sw3[el][p][lane] =
                b[0] * c[0] + b[1] * c[4] + b[2] * c[8] + b[3] * c[12];
        }

        #pragma unroll
        for (int p = 0; p < NP4; p++) {
            const float* b  = bx + sp4[p * 4 + 1] * 4;
            const float* c2 = bx + sp4[p * 4 + 2] * 4;
            const float* C  = sC4 + p * 256 + i_idx * 64 + km; // j stride 16, k stride 4
            float w = 0.f;
            #pragma unroll
            for (int j = 0; j < 4; j++) {
                float t = c2[0] * C[j * 16 + 0] + c2[1] * C[j * 16 + 4]
                        + c2[2] * C[j * 16 + 8] + c2[3] * C[j * 16 + 12];
                w = fmaf(b[j], t, w);
            }
            sw4[el][p][lane] = w;
        }
    }
    __syncwarp();

    // ---- phase 2: gather a-vectors, contract against shared weights, store ----
    float4 a3[NP3], a4[NP4];
    if (active) {
        const int row = __ldg(i0 + e);
        const float* x0r = x0 + (size_t)row * X0_ROW + lane * 4;  // [s0][u][i], u = lane
        #pragma unroll
        for (int p = 0; p < NP3; p++)
            a3[p] = *(const float4*)(x0r + sp3[p * 3 + 0] * (MUL * D));
        #pragma unroll
        for (int p = 0; p < NP4; p++)
            a4[p] = *(const float4*)(x0r + sp4[p * 4 + 0] * (MUL * D));
    } else {
        #pragma unroll
        for (int p = 0; p < NP3; p++) a3[p] = make_float4(0.f, 0.f, 0.f, 0.f);
        #pragma unroll
        for (int p = 0; p < NP4; p++) a4[p] = make_float4(0.f, 0.f, 0.f, 0.f);
    }

    float* outr = out + e * OUT_ROW + lane * 4;

    #pragma unroll
    for (int so = 0; so < SOUT; so++) {
        float4 acc = make_float4(0.f, 0.f, 0.f, 0.f);

        #pragma unroll
        for (int p = 0; p < NP3; p++) {
            if (sp3[p * 3 + 2] == so) {      // uniform across block -> cheap branch
                const float4* w = (const float4*)sw3[el][p];
                const float4 w0 = w[0], w1 = w[1], w2 = w[2], w3v = w[3];
                const float4 a = a3[p];
                acc.x = fmaf(a.x, w0.x, fmaf(a.y, w1.x, fmaf(a.z, w2.x, fmaf(a.w, w3v.x, acc.x))));
                acc.y = fmaf(a.x, w0.y, fmaf(a.y, w1.y, fmaf(a.z, w2.y, fmaf(a.w, w3v.y, acc.y))));
                acc.z = fmaf(a.x, w0.z, fmaf(a.y, w1.z, fmaf(a.z, w2.z, fmaf(a.w, w3v.z, acc.z))));
                acc.w = fmaf(a.x, w0.w, fmaf(a.y, w1.w, fmaf(a.z, w2.w, fmaf(a.w, w3v.w, acc.w))));
            }
        }

        #pragma unroll
        for (int p = 0; p < NP4; p++) {
            if (sp4[p * 4 + 3] == so) {
                const float4* w = (const float4*)sw4[el][p];
                const float4 w0 = w[0], w1 = w[1], w2 = w[2], w3v = w[3];
                const float4 a = a4[p];
                acc.x = fmaf(a.x, w0.x, fmaf(a.y, w1.x, fmaf(a.z, w2.x, fmaf(a.w, w3v.x, acc.x))));
                acc.y = fmaf(a.x, w0.y, fmaf(a.y, w1.y, fmaf(a.z, w2.y, fmaf(a.w, w3v.y, acc.y))));
                acc.z = fmaf(a.x, w0.z, fmaf(a.y, w1.z, fmaf(a.z, w2.z, fmaf(a.w, w3v.z, acc.z))));
                acc.w = fmaf(a.x, w0.w, fmaf(a.y, w1.w, fmaf(a.z, w2.w, fmaf(a.w, w3v.w, acc.w))));
            }
        }

        if (active) *(float4*)(outr + so * (MUL * D)) = acc;
    }
}

} // anonymous namespace

extern "C" void kernel_launch(void* const* d_in, const int* in_sizes, int n_in,
                              void* d_out, int out_size)
{
    const float* x0 = (const float*)d_in[0];
    const int*   i0 = (const int*)  d_in[1];
    const float* x1 = (const float*)d_in[2];
    const float* C3 = (const float*)d_in[3];
    const float* C4 = (const float*)d_in[4];
    const int*   p3 = (const int*)  d_in[5];
    const int*   p4 = (const int*)  d_in[6];
    float* out = (float*)d_out;

    const int E = in_sizes[1];                 // i0 element count
    const int blocks = (E + EPB - 1) / EPB;
    tp_fused_kernel<<<blocks, THREADS>>>(x0, i0, x1, C3, C4, p3, p4, out, E);
}

// round 2
// speedup vs baseline: 1.0319x; 1.0319x over previous
#include <cuda_runtime.h>

namespace {

constexpr int MUL  = 16;
constexpr int D    = 4;
constexpr int S1   = 8;
constexpr int SOUT = 8;
constexpr int NP3  = 8;
constexpr int NP4  = 4;

constexpr int X0_ROW  = 8 * MUL * D;     // 512 floats
constexpr int X1_ROW  = S1 * D;          // 32
constexpr int OUT_ROW = SOUT * MUL * D;  // 512

constexpr int EPB     = 16;
constexpr int THREADS = 256;

// padded row strides (all +4 words so edge-stride mod 32 != 0 -> no bank conflicts)
constexpr int X1P = X1_ROW + 4;          // 36
constexpr int W3P = NP3 * 16 + 4;        // 132
constexpr int W4P = NP4 * 16 + 4;        // 68

__global__ void __launch_bounds__(THREADS)
tp_v2_kernel(const float* __restrict__ x0,
             const int*   __restrict__ i0,
             const float* __restrict__ x1,
             const float* __restrict__ gC3,
             const float* __restrict__ gC4,
             const int*   __restrict__ gp3,
             const int*   __restrict__ gp4,
             float*       __restrict__ out,
             int E)
{
    __shared__ __align__(16) float sx1[EPB][X1P];
    __shared__ __align__(16) float sw3[EPB][W3P];
    __shared__ __align__(16) float sw4[EPB][W4P];
    __shared__ int sp3[NP3 * 3];
    __shared__ int sp4[NP4 * 4];

    const int  tid = threadIdx.x;
    const long e0  = (long)blockIdx.x * EPB;

    // ---- stage path metadata into smem ----
    if (tid < NP3 * 3)                    sp3[tid]           = gp3[tid];
    else if (tid < NP3 * 3 + NP4 * 4)     sp4[tid - NP3 * 3] = gp4[tid - NP3 * 3];

    // ---- stage x1 rows for the block's 16 edges (read-once -> evict-first) ----
    if (tid < 128) {
        const int el = tid >> 3, part = tid & 7;
        const long ee = e0 + el;
        if (ee < (long)E) {
            float4 v = __ldcs((const float4*)(x1 + ee * X1_ROW) + part);
            *(float4*)&sx1[el][part * 4] = v;
        }
    }

    // ---- phase-1 thread roles: C slice lives in REGISTERS (edge-invariant) ----
    // tid   0..127 : w3 cell (p = tid>>4, cell = tid&15 -> (i,k)), 4 C3 floats
    // tid 128..191 : w4 cell (p = (tid-128)>>4, cell -> (i,m)),   16 C4 floats
    const int cell = tid & 15, ci = cell >> 2, ck = cell & 3;
    float c3r[4];
    float c4r[16];
    int slotB = 0, slotC = 0;
    if (tid < 128) {
        const int p = tid >> 4;
        slotB = __ldg(gp3 + p * 3 + 1);
        #pragma unroll
        for (int j = 0; j < 4; j++)
            c3r[j] = __ldg(gC3 + p * 64 + ci * 16 + j * 4 + ck);
    } else if (tid < 192) {
        const int p = (tid - 128) >> 4;
        slotB = __ldg(gp4 + p * 4 + 1);
        slotC = __ldg(gp4 + p * 4 + 2);
        #pragma unroll
        for (int j = 0; j < 4; j++)
            #pragma unroll
            for (int k = 0; k < 4; k++)
                c4r[j * 4 + k] = __ldg(gC4 + p * 256 + ci * 64 + j * 16 + k * 4 + ck);
    }

    __syncthreads();

    // ---- issue phase-2 gather loads EARLY (overlap latency with phase-1 math) ----
    const int  el   = tid >> 4;
    const int  lane = tid & 15;
    const long e    = e0 + el;
    const bool act  = (e < (long)E);

    float4 a3[NP3], a4[NP4];
    int so3[NP3], so4[NP4];
    {
        const int row = act ? __ldg(i0 + e) : 0;
        const float* x0r = x0 + (size_t)row * X0_ROW + lane * 4;
        #pragma unroll
        for (int p = 0; p < NP3; p++) {
            so3[p] = sp3[p * 3 + 2];
            a3[p]  = *(const float4*)(x0r + sp3[p * 3 + 0] * (MUL * D));
        }
        #pragma unroll
        for (int p = 0; p < NP4; p++) {
            so4[p] = sp4[p * 4 + 3];
            a4[p]  = *(const float4*)(x0r + sp4[p * 4 + 0] * (MUL * D));
        }
    }

    // ---- phase 1: compute per-edge path weights, C in registers ----
    if (tid < 128) {
        const int p = tid >> 4;
        #pragma unroll
        for (int e1 = 0; e1 < EPB; e1++) {
            const float4 b = *(const float4*)&sx1[e1][slotB * 4];
            sw3[e1][p * 16 + cell] =
                fmaf(b.x, c3r[0], fmaf(b.y, c3r[1], fmaf(b.z, c3r[2], b.w * c3r[3])));
        }
    } else if (tid < 192) {
        const int p = (tid - 128) >> 4;
        #pragma unroll
        for (int e1 = 0; e1 < EPB; e1++) {
            const float4 b = *(const float4*)&sx1[e1][slotB * 4];
            const float4 c = *(const float4*)&sx1[e1][slotC * 4];
            float w = 0.f;
            #pragma unroll
            for (int j = 0; j < 4; j++) {
                const float t = fmaf(c.x, c4r[j * 4 + 0],
                                fmaf(c.y, c4r[j * 4 + 1],
                                fmaf(c.z, c4r[j * 4 + 2],
                                     c.w * c4r[j * 4 + 3])));
                w = fmaf((&b.x)[j], t, w);
            }
            sw4[e1][p * 16 + cell] = w;
        }
    }

    __syncthreads();

    // ---- phase 2: contract gathered a-vectors against shared weights ----
    float* outr = out + e * OUT_ROW + lane * 4;

    #pragma unroll
    for (int so = 0; so < SOUT; so++) {
        float4 acc = make_float4(0.f, 0.f, 0.f, 0.f);

        #pragma unroll
        for (int p = 0; p < NP3; p++) {
            if (so3[p] == so) {   // uniform across block -> cheap branch
                const float4* w = (const float4*)&sw3[el][p * 16];
                const float4 w0 = w[0], w1 = w[1], w2 = w[2], w3v = w[3];
                const float4 a = a3[p];
                acc.x = fmaf(a.x, w0.x, fmaf(a.y, w1.x, fmaf(a.z, w2.x, fmaf(a.w, w3v.x, acc.x))));
                acc.y = fmaf(a.x, w0.y, fmaf(a.y, w1.y, fmaf(a.z, w2.y, fmaf(a.w, w3v.y, acc.y))));
                acc.z = fmaf(a.x, w0.z, fmaf(a.y, w1.z, fmaf(a.z, w2.z, fmaf(a.w, w3v.z, acc.z))));
                acc.w = fmaf(a.x, w0.w, fmaf(a.y, w1.w, fmaf(a.z, w2.w, fmaf(a.w, w3v.w, acc.w))));
            }
        }

        #pragma unroll
        for (int p = 0; p < NP4; p++) {
            if (so4[p] == so) {
                const float4* w = (const float4*)&sw4[el][p * 16];
                const float4 w0 = w[0], w1 = w[1], w2 = w[2], w3v = w[3];
                const float4 a = a4[p];
                acc.x = fmaf(a.x, w0.x, fmaf(a.y, w1.x, fmaf(a.z, w2.x, fmaf(a.w, w3v.x, acc.x))));
                acc.y = fmaf(a.x, w0.y, fmaf(a.y, w1.y, fmaf(a.z, w2.y, fmaf(a.w, w3v.y, acc.y))));
                acc.z = fmaf(a.x, w0.z, fmaf(a.y, w1.z, fmaf(a.z, w2.z, fmaf(a.w, w3v.z, acc.z))));
                acc.w = fmaf(a.x, w0.w, fmaf(a.y, w1.w, fmaf(a.z, w2.w, fmaf(a.w, w3v.w, acc.w))));
            }
        }

        if (act) __stcs((float4*)(outr + so * (MUL * D)), acc);
    }
}

} // anonymous namespace

extern "C" void kernel_launch(void* const* d_in, const int* in_sizes, int n_in,
                              void* d_out, int out_size)
{
    const float* x0 = (const float*)d_in[0];
    const int*   i0 = (const int*)  d_in[1];
    const float* x1 = (const float*)d_in[2];
    const float* C3 = (const float*)d_in[3];
    const float* C4 = (const float*)d_in[4];
    const int*   p3 = (const int*)  d_in[5];
    const int*   p4 = (const int*)  d_in[6];
    float* out = (float*)d_out;

    const int E = in_sizes[1];
    const int blocks = (E + EPB - 1) / EPB;
    tp_v2_kernel<<<blocks, THREADS>>>(x0, i0, x1, C3, C4, p3, p4, out, E);
}